// round 4
// baseline (speedup 1.0000x reference)
#include <cuda_runtime.h>
#include <cuda_fp16.h>
#include <cstdint>

// GRU_84490596647263: 2-layer GRU, B=64, T=512, D=H=1024, FC -> [64,1]
//
// Single persistent kernel: 128 blocks (one per SM), weights resident in SMEM,
// fp16 mma.sync tensor-core GEMMs with fp32 accumulation, fp32 hidden state
// kept locally per owner block, software grid barrier once per pipelined
// interval (layer 1 lags layer 0 by one step).

#define NBLK    128
#define NTHR    256
#define WROW    1032                      // padded row length in halves (1024 + 8)
#define SMEM_W_HALVES (96 * WROW)         // 96 weight rows
#define SMEM_BYTES (SMEM_W_HALVES * 2 + 64 * 16 * 4)

// ---------------- device globals (no cudaMalloc allowed) -------------------
__device__ __half g_x16[64u * 512u * 1024u];   // x converted to fp16, [t][b][d]
__device__ __half g_h0[2][64 * 1024];          // double-buffered layer-0 hidden (fp16)
__device__ __half g_h1[2][64 * 1024];          // double-buffered layer-1 hidden (fp16)
__device__ float  g_part[64 * 64];             // FC partials [block][batch]
__device__ int          g_cnt = 0;
__device__ volatile int g_sense = 0;

// ---------------- helpers --------------------------------------------------
__device__ __forceinline__ void mma16816(float* c, const uint32_t* a,
                                         uint32_t b0, uint32_t b1) {
    asm volatile(
        "mma.sync.aligned.m16n8k16.row.col.f32.f16.f16.f32 "
        "{%0,%1,%2,%3}, {%4,%5,%6,%7}, {%8,%9}, {%0,%1,%2,%3};\n"
        : "+f"(c[0]), "+f"(c[1]), "+f"(c[2]), "+f"(c[3])
        : "r"(a[0]), "r"(a[1]), "r"(a[2]), "r"(a[3]), "r"(b0), "r"(b1));
}

// Sense-reversing grid barrier. __threadfence() is gpu-scope -> emits
// CCTL.IVALL on sm_103a, invalidating this SM's L1D, so normal (L1-cached)
// loads of the h buffers after the barrier observe fresh data.
__device__ __forceinline__ void grid_bar(int nb, int& sense) {
    __syncthreads();
    if (threadIdx.x == 0) {
        int next = sense ^ 1;
        __threadfence();
        if (atomicAdd(&g_cnt, 1) == nb - 1) {
            atomicExch(&g_cnt, 0);
            __threadfence();
            g_sense = next;
        } else {
            while (g_sense != next) { }
        }
        __threadfence();
    }
    __syncthreads();
    sense ^= 1;
}

__device__ __forceinline__ float sigmf(float v) {
    return 1.0f / (1.0f + __expf(-v));
}

// ---------------- x fp32 -> fp16 transpose kernel --------------------------
// src: x[b][t][d] fp32; dst: g_x16[t][b][d] fp16. 4 elements / thread.
__global__ void cvt_x_kernel(const float* __restrict__ x) {
    size_t i  = (size_t)blockIdx.x * blockDim.x + threadIdx.x;
    size_t s4 = i << 2;
    int b = (int)(s4 >> 19);          // 512*1024 = 2^19
    int t = (int)((s4 >> 10) & 511);
    int d = (int)(s4 & 1023);
    float4 v = *(const float4*)(x + s4);
    __half2 p0 = __floats2half2_rn(v.x, v.y);
    __half2 p1 = __floats2half2_rn(v.z, v.w);
    size_t dsti = (((size_t)t * 64 + b) << 10) + d;
    __half2* dst = (__half2*)(g_x16 + dsti);
    dst[0] = p0; dst[1] = p1;
}

// ---------------- persistent GRU kernel ------------------------------------
__global__ void __launch_bounds__(NTHR, 1)
gru_persist(const float* __restrict__ Wx0, const float* __restrict__ bx0,
            const float* __restrict__ Wh0, const float* __restrict__ bh0,
            const float* __restrict__ Wx1, const float* __restrict__ bx1,
            const float* __restrict__ Wh1, const float* __restrict__ bh1,
            const float* __restrict__ fcW, const float* __restrict__ fcb,
            float* __restrict__ out) {
    extern __shared__ char smem[];
    __half* Wsm     = (__half*)smem;                         // [96][WROW]
    float*  h_local = (float*)(smem + SMEM_W_HALVES * 2);    // [64][16] fp32 state

    const int tid  = threadIdx.x;
    const int blk  = blockIdx.x;
    const int L    = blk >> 6;           // 0 or 1
    const int j0   = (blk & 63) << 4;    // first hidden unit owned (16 units)
    const int lane = tid & 31;
    const int w    = tid >> 5;
    const int mt   = w & 3;              // row tile (16 rows each)
    const int uh   = w >> 2;             // unit half (8 units each)
    const int g    = lane >> 2;          // mma groupID
    const int tig  = lane & 3;           // thread-in-group

    const float* Wx = L ? Wx1 : Wx0;
    const float* Wh = L ? Wh1 : Wh0;
    const float* bx = L ? bx1 : bx0;
    const float* bh = L ? bh1 : bh0;

    // ---- load weight slice into SMEM as fp16 (rows: 0-2 = Wx r,z,n; 3-5 = Wh) ----
    for (int idx = tid; idx < 96 * 256; idx += NTHR) {
        int r  = idx >> 8;               // 0..95
        int k4 = (idx & 255) << 2;       // 0..1020 step 4
        int g6 = r >> 4, u = r & 15;
        const float* src = (g6 < 3)
            ? Wx + ((size_t)((g6 << 10) + j0 + u) << 10) + k4
            : Wh + ((size_t)((((g6 - 3)) << 10) + j0 + u) << 10) + k4;
        float4 v = *(const float4*)src;
        __half2* dst = (__half2*)(Wsm + r * WROW + k4);
        dst[0] = __floats2half2_rn(v.x, v.y);
        dst[1] = __floats2half2_rn(v.z, v.w);
    }
    // ---- zero local fp32 state and global fp16 h buffers (own slice) ----
    for (int idx = tid; idx < 64 * 16; idx += NTHR) h_local[idx] = 0.0f;
    {
        __half z = __float2half(0.0f);
        for (int idx = tid; idx < 64 * 16; idx += NTHR) {
            int b = idx >> 4, u = idx & 15;
            int off = b * 1024 + j0 + u;
            if (L == 0) { g_h0[0][off] = z; g_h0[1][off] = z; }
            else        { g_h1[0][off] = z; g_h1[1][off] = z; }
        }
    }
    // ---- per-thread bias registers (accumulator init values) ----
    float bias0[6], bias1[6];
    {
        int col = j0 + (uh << 3) + (tig << 1);
        #pragma unroll
        for (int f = 0; f < 3; f++) {
            bias0[f]     = bx[(f << 10) + col];
            bias1[f]     = bx[(f << 10) + col + 1];
            bias0[3 + f] = bh[(f << 10) + col];
            bias1[3 + f] = bh[(f << 10) + col + 1];
        }
    }
    __syncthreads();

    int sense = g_sense;                 // stable value from previous launch
    grid_bar(NBLK, sense);               // init complete everywhere

    const int rbase = (mt << 4) + g;     // c0 row; c2 row = rbase + 8
    const int un    = (uh << 3) + g;     // B-fragment unit index (0..15)
    const uint32_t* Wsm32 = (const uint32_t*)Wsm;  // row stride 516 words
    int brow[6];
    #pragma unroll
    for (int f = 0; f < 6; f++) brow[f] = (f * 16 + un) * (WROW / 2);

    const int o0 = (rbase * 1024 + (tig << 1)) * 2;  // A byte offsets
    const int o1 = o0 + 8 * 1024 * 2;

    for (int t = 0; t <= 512; t++) {
        bool active = (L == 0) ? (t < 512) : (t >= 1);
        if (active) {
            const char* Ax;
            const char* Ah;
            if (L == 0) {
                Ax = (const char*)(g_x16 + (size_t)t * 65536);   // x_t slab
                Ah = (const char*)g_h0[(t + 1) & 1];             // h0(t-1)
            } else {
                Ax = (const char*)g_h0[(t - 1) & 1];             // h0(t-1)
                Ah = (const char*)g_h1[t & 1];                   // h1(t-2)
            }
            float acc[6][4];
            #pragma unroll
            for (int f = 0; f < 6; f++) {
                acc[f][0] = bias0[f]; acc[f][1] = bias1[f];
                acc[f][2] = bias0[f]; acc[f][3] = bias1[f];
            }
            #pragma unroll 4
            for (int kk = 0; kk < 64; kk++) {
                const int koff = kk << 5;                        // bytes
                uint32_t A0[4], A1[4];
                A0[0] = *(const uint32_t*)(Ax + o0 + koff);
                A0[1] = *(const uint32_t*)(Ax + o1 + koff);
                A0[2] = *(const uint32_t*)(Ax + o0 + koff + 16);
                A0[3] = *(const uint32_t*)(Ax + o1 + koff + 16);
                A1[0] = *(const uint32_t*)(Ah + o0 + koff);
                A1[1] = *(const uint32_t*)(Ah + o1 + koff);
                A1[2] = *(const uint32_t*)(Ah + o0 + koff + 16);
                A1[3] = *(const uint32_t*)(Ah + o1 + koff + 16);
                const int kw = (kk << 3) + tig;
                #pragma unroll
                for (int f = 0; f < 6; f++) {
                    uint32_t b0 = Wsm32[brow[f] + kw];
                    uint32_t b1 = Wsm32[brow[f] + kw + 4];
                    mma16816(acc[f], (f < 3) ? A0 : A1, b0, b1);
                }
            }
            // ---- gate epilogue (all in fp32) ----
            float hn_new[4];
            #pragma unroll
            for (int p = 0; p < 4; p++) {
                float r = sigmf(acc[0][p] + acc[3][p]);
                float z = sigmf(acc[1][p] + acc[4][p]);
                float n = tanhf(acc[2][p] + r * acc[5][p]);
                int row = rbase + ((p >> 1) << 3);
                int u   = (uh << 3) + (tig << 1) + (p & 1);
                float ho = h_local[row * 16 + u];
                float hv = n + z * (ho - n);
                h_local[row * 16 + u] = hv;
                hn_new[p] = hv;
            }
            __half* dst = (L == 0) ? g_h0[t & 1] : g_h1[(t - 1) & 1];
            int col = j0 + (uh << 3) + (tig << 1);
            *(__half2*)(dst + rbase * 1024 + col) =
                __floats2half2_rn(hn_new[0], hn_new[1]);
            *(__half2*)(dst + (rbase + 8) * 1024 + col) =
                __floats2half2_rn(hn_new[2], hn_new[3]);
        }
        grid_bar(NBLK, sense);
    }

    // ---- final FC: out = h1(511) @ fcW^T + fcb (deterministic 2-stage) ----
    if (L == 1) {
        for (int b = tid; b < 64; b += NTHR) {
            float s = 0.0f;
            #pragma unroll
            for (int u = 0; u < 16; u++)
                s += h_local[b * 16 + u] * fcW[j0 + u];
            g_part[(blk - 64) * 64 + b] = s;
        }
    }
    grid_bar(NBLK, sense);
    if (blk == 0) {
        for (int b = tid; b < 64; b += NTHR) {
            float s = fcb[0];
            for (int jb = 0; jb < 64; jb++) s += g_part[jb * 64 + b];
            out[b] = s;
        }
    }
}

// ---------------- launch ----------------------------------------------------
extern "C" void kernel_launch(void* const* d_in, const int* in_sizes, int n_in,
                              void* d_out, int out_size) {
    const float* x   = (const float*)d_in[0];
    const float* Wx0 = (const float*)d_in[1];
    const float* bx0 = (const float*)d_in[2];
    const float* Wh0 = (const float*)d_in[3];
    const float* bh0 = (const float*)d_in[4];
    const float* Wx1 = (const float*)d_in[5];
    const float* bx1 = (const float*)d_in[6];
    const float* Wh1 = (const float*)d_in[7];
    const float* bh1 = (const float*)d_in[8];
    const float* fcW = (const float*)d_in[9];
    const float* fcb = (const float*)d_in[10];
    float* out = (float*)d_out;

    cudaFuncSetAttribute(gru_persist,
                         cudaFuncAttributeMaxDynamicSharedMemorySize,
                         SMEM_BYTES);

    // 64*512*1024 elems / 4 per thread / 256 threads = 32768 blocks
    cvt_x_kernel<<<32768, 256>>>(x);
    gru_persist<<<NBLK, NTHR, SMEM_BYTES>>>(Wx0, bx0, Wh0, bh0,
                                            Wx1, bx1, Wh1, bh1,
                                            fcW, fcb, out);
    (void)in_sizes; (void)n_in; (void)out_size;
}

// round 5
// speedup vs baseline: 1.6919x; 1.6919x over previous
#include <cuda_runtime.h>
#include <cuda_fp16.h>
#include <cstdint>

// GRU_84490596647263: 2-layer GRU, B=64, T=512, D=H=1024, FC -> [64,1]
//
// Persistent kernel, weights in SMEM, fp16 mma.sync with fp32 accum.
// R5 change: all A operands (x slabs, h buffers) are stored in global memory
// PRE-SWIZZLED into mma-fragment order, so each thread's A fragment is one
// coalesced LDG.128 instead of 8 scattered LDG.32 (L1 wavefronts 8x down).

#define NBLK    128
#define NTHR    256
#define WROW    1032                      // padded weight row (halves)
#define SMEM_W_HALVES (96 * WROW)
#define SMEM_BYTES (SMEM_W_HALVES * 2 + 64 * 16 * 4)

// Swizzled slab layout for a [64 x 1024] fp16 A matrix (65536 halves):
//   element (b, j):  kk=j>>4, mt=b>>4, r=b&15, c=j&15, g=r&7,
//                    w=(r>>3)+2*(c>>3), tig=(c>>1)&3, half=c&1
//   half-offset = ((kk*4+mt)*32 + g*4 + tig)*8 + w*2 + half
// => lane (g*4+tig) of tile (kk,mt) holds uint4 {a0,a1,a2,a3} contiguously.

// ---------------- device globals -------------------------------------------
__device__ __half g_x16[64u * 512u * 1024u];   // x, swizzled per-t slabs
__device__ __half g_h0[2][65536];              // layer-0 hidden (swizzled)
__device__ __half g_h1[2][65536];              // layer-1 hidden (swizzled)
__device__ float  g_part[64 * 64];
__device__ int          g_cnt = 0;
__device__ volatile int g_sense = 0;

// ---------------- helpers --------------------------------------------------
__device__ __forceinline__ void mma16816(float* c, const uint4& A,
                                         uint32_t b0, uint32_t b1) {
    asm volatile(
        "mma.sync.aligned.m16n8k16.row.col.f32.f16.f16.f32 "
        "{%0,%1,%2,%3}, {%4,%5,%6,%7}, {%8,%9}, {%0,%1,%2,%3};\n"
        : "+f"(c[0]), "+f"(c[1]), "+f"(c[2]), "+f"(c[3])
        : "r"(A.x), "r"(A.y), "r"(A.z), "r"(A.w), "r"(b0), "r"(b1));
}

__device__ __forceinline__ void grid_bar(int nb, int& sense) {
    __syncthreads();
    if (threadIdx.x == 0) {
        int next = sense ^ 1;
        __threadfence();                       // release + L1 invalidate
        if (atomicAdd(&g_cnt, 1) == nb - 1) {
            atomicExch(&g_cnt, 0);
            __threadfence();
            g_sense = next;
        } else {
            while (g_sense != next) { }
        }
        __threadfence();                       // acquire + L1 invalidate
    }
    __syncthreads();
    sense ^= 1;
}

__device__ __forceinline__ float sigmf(float v) {
    return 1.0f / (1.0f + __expf(-v));
}

// ---------------- x fp32 -> fp16 swizzle kernel ----------------------------
// src x[b][t][j] fp32 -> g_x16 swizzled slab per t. 4 j's per thread.
__global__ void cvt_x_kernel(const float* __restrict__ x) {
    size_t i  = (size_t)blockIdx.x * blockDim.x + threadIdx.x;
    size_t s4 = i << 2;
    int b = (int)(s4 >> 19);          // 512*1024 = 2^19
    int t = (int)((s4 >> 10) & 511);
    int j = (int)(s4 & 1023);         // multiple of 4
    float4 v = *(const float4*)(x + s4);
    int kk = j >> 4, c = j & 15;
    int mt = b >> 4, r = b & 15;
    int g  = r & 7;
    int w  = (r >> 3) + 2 * (c >> 3);
    int tig = (c >> 1) & 3;
    __half* slab = g_x16 + (size_t)t * 65536;
    size_t base = ((size_t)(kk * 4 + mt) * 32 + g * 4 + tig) * 8 + w * 2;
    *(__half2*)(slab + base)     = __floats2half2_rn(v.x, v.y);
    *(__half2*)(slab + base + 8) = __floats2half2_rn(v.z, v.w);  // tig+1 lane
}

// ---------------- persistent GRU kernel ------------------------------------
__global__ void __launch_bounds__(NTHR, 1)
gru_persist(const float* __restrict__ Wx0, const float* __restrict__ bx0,
            const float* __restrict__ Wh0, const float* __restrict__ bh0,
            const float* __restrict__ Wx1, const float* __restrict__ bx1,
            const float* __restrict__ Wh1, const float* __restrict__ bh1,
            const float* __restrict__ fcW, const float* __restrict__ fcb,
            float* __restrict__ out) {
    extern __shared__ char smem[];
    __half* Wsm     = (__half*)smem;                         // [96][WROW]
    float*  h_local = (float*)(smem + SMEM_W_HALVES * 2);    // [64][16] fp32

    const int tid  = threadIdx.x;
    const int blk  = blockIdx.x;
    const int L    = blk >> 6;
    const int kb   = blk & 63;           // owned kk-block / unit block
    const int j0   = kb << 4;
    const int lane = tid & 31;
    const int w    = tid >> 5;
    const int mt   = w & 3;
    const int uh   = w >> 2;
    const int g    = lane >> 2;
    const int tig  = lane & 3;

    const float* Wx = L ? Wx1 : Wx0;
    const float* Wh = L ? Wh1 : Wh0;
    const float* bx = L ? bx1 : bx0;
    const float* bh = L ? bh1 : bh0;

    // ---- weights -> SMEM fp16 (rows 0-47 = Wx r,z,n; 48-95 = Wh) ----
    for (int idx = tid; idx < 96 * 256; idx += NTHR) {
        int r  = idx >> 8;
        int k4 = (idx & 255) << 2;
        int g6 = r >> 4, u = r & 15;
        const float* src = (g6 < 3)
            ? Wx + ((size_t)((g6 << 10) + j0 + u) << 10) + k4
            : Wh + ((size_t)(((g6 - 3) << 10) + j0 + u) << 10) + k4;
        float4 v = *(const float4*)src;
        __half2* dst = (__half2*)(Wsm + r * WROW + k4);
        dst[0] = __floats2half2_rn(v.x, v.y);
        dst[1] = __floats2half2_rn(v.z, v.w);
    }
    // ---- zero local fp32 state + owned slices of global h slabs ----
    for (int idx = tid; idx < 64 * 16; idx += NTHR) h_local[idx] = 0.0f;
    {
        // block's slice in the swizzled slab is contiguous: [kb*1024, kb*1024+1024)
        uint2 z = make_uint2(0u, 0u);
        size_t off = (size_t)kb * 1024 + (size_t)tid * 4;   // 4 halves / thread
        if (L == 0) {
            *(uint2*)(g_h0[0] + off) = z;
            *(uint2*)(g_h0[1] + off) = z;
        } else {
            *(uint2*)(g_h1[0] + off) = z;
            *(uint2*)(g_h1[1] + off) = z;
        }
    }
    // ---- bias registers ----
    float bias0[6], bias1[6];
    {
        int col = j0 + (uh << 3) + (tig << 1);
        #pragma unroll
        for (int f = 0; f < 3; f++) {
            bias0[f]     = bx[(f << 10) + col];
            bias1[f]     = bx[(f << 10) + col + 1];
            bias0[3 + f] = bh[(f << 10) + col];
            bias1[3 + f] = bh[(f << 10) + col + 1];
        }
    }
    __syncthreads();

    int sense = g_sense;
    grid_bar(NBLK, sense);

    const int rbase = (mt << 4) + g;
    const int un    = (uh << 3) + g;
    const uint32_t* Wsm32 = (const uint32_t*)Wsm;     // row stride WROW/2 = 516
    int brow[6];
    #pragma unroll
    for (int f = 0; f < 6; f++) brow[f] = (f * 16 + un) * (WROW / 2);

    const int laneblk = mt * 32 + g * 4 + tig;        // uint4 index in kk-block

    for (int t = 0; t <= 512; t++) {
        bool active = (L == 0) ? (t < 512) : (t >= 1);
        if (active) {
            const uint4* Ax;
            const uint4* Ah;
            if (L == 0) {
                Ax = (const uint4*)(g_x16 + (size_t)t * 65536);
                Ah = (const uint4*)g_h0[(t + 1) & 1];
            } else {
                Ax = (const uint4*)g_h0[(t - 1) & 1];
                Ah = (const uint4*)g_h1[t & 1];
            }
            float acc[6][4];
            #pragma unroll
            for (int f = 0; f < 6; f++) {
                acc[f][0] = bias0[f]; acc[f][1] = bias1[f];
                acc[f][2] = bias0[f]; acc[f][3] = bias1[f];
            }
            #pragma unroll 4
            for (int kk = 0; kk < 64; kk++) {
                uint4 A0 = Ax[kk * 128 + laneblk];    // one coalesced LDG.128
                uint4 A1 = Ah[kk * 128 + laneblk];
                const int kw = (kk << 3) + tig;
                #pragma unroll
                for (int f = 0; f < 6; f++) {
                    uint32_t b0 = Wsm32[brow[f] + kw];
                    uint32_t b1 = Wsm32[brow[f] + kw + 4];
                    mma16816(acc[f], (f < 3) ? A0 : A1, b0, b1);
                }
            }
            // ---- gate epilogue (fp32) ----
            float hn_new[4];
            #pragma unroll
            for (int p = 0; p < 4; p++) {
                float r = sigmf(acc[0][p] + acc[3][p]);
                float z = sigmf(acc[1][p] + acc[4][p]);
                float n = tanhf(acc[2][p] + r * acc[5][p]);
                int row = rbase + ((p >> 1) << 3);
                int u   = (uh << 3) + (tig << 1) + (p & 1);
                float ho = h_local[row * 16 + u];
                float hv = n + z * (ho - n);
                h_local[row * 16 + u] = hv;
                hn_new[p] = hv;
            }
            // single 8B store into the swizzled slab
            __half* dst = (L == 0) ? g_h0[t & 1] : g_h1[(t - 1) & 1];
            size_t hoff = ((size_t)(kb * 4 + mt) * 32 + g * 4 + tig) * 8
                          + (size_t)uh * 4;
            __half2 lo = __floats2half2_rn(hn_new[0], hn_new[1]); // w = 2*uh
            __half2 hi = __floats2half2_rn(hn_new[2], hn_new[3]); // w = 2*uh+1
            uint2 pk;
            pk.x = *(const uint32_t*)&lo;
            pk.y = *(const uint32_t*)&hi;
            *(uint2*)(dst + hoff) = pk;
        }
        grid_bar(NBLK, sense);
    }

    // ---- final FC (deterministic 2-stage) ----
    if (L == 1) {
        for (int b = tid; b < 64; b += NTHR) {
            float s = 0.0f;
            #pragma unroll
            for (int u = 0; u < 16; u++)
                s += h_local[b * 16 + u] * fcW[j0 + u];
            g_part[kb * 64 + b] = s;
        }
    }
    grid_bar(NBLK, sense);
    if (blk == 0) {
        for (int b = tid; b < 64; b += NTHR) {
            float s = fcb[0];
            for (int jb = 0; jb < 64; jb++) s += g_part[jb * 64 + b];
            out[b] = s;
        }
    }
}

// ---------------- launch ----------------------------------------------------
extern "C" void kernel_launch(void* const* d_in, const int* in_sizes, int n_in,
                              void* d_out, int out_size) {
    const float* x   = (const float*)d_in[0];
    const float* Wx0 = (const float*)d_in[1];
    const float* bx0 = (const float*)d_in[2];
    const float* Wh0 = (const float*)d_in[3];
    const float* bh0 = (const float*)d_in[4];
    const float* Wx1 = (const float*)d_in[5];
    const float* bx1 = (const float*)d_in[6];
    const float* Wh1 = (const float*)d_in[7];
    const float* bh1 = (const float*)d_in[8];
    const float* fcW = (const float*)d_in[9];
    const float* fcb = (const float*)d_in[10];
    float* out = (float*)d_out;

    cudaFuncSetAttribute(gru_persist,
                         cudaFuncAttributeMaxDynamicSharedMemorySize,
                         SMEM_BYTES);

    cvt_x_kernel<<<32768, 256>>>(x);
    gru_persist<<<NBLK, NTHR, SMEM_BYTES>>>(Wx0, bx0, Wh0, bh0,
                                            Wx1, bx1, Wh1, bh1,
                                            fcW, fcb, out);
    (void)in_sizes; (void)n_in; (void)out_size;
}